// round 17
// baseline (speedup 1.0000x reference)
#include <cuda_runtime.h>

#define NN 100000
#define NE 1000000
#define NBS ((NN + 255) / 256)  // 391 scan blocks

// ---- scratch (static device globals: allocation-free) ----
__device__ int g_is64;           // 1 if edge_index is int64, 0 if int32
__device__ int g_cnt[NN];
__device__ int g_tmp[NN];
__device__ int g_row[NN + 1];
__device__ int g_cur[NN];
__device__ int g_col[NE];
__device__ int g_bsums[NBS];
__device__ int g_boff[NBS + 1];
__device__ __align__(16) float g_agg[NN * 64];
__device__ __align__(16) float g_h[NN * 64];
__device__ __align__(16) float g_h2[NN * 64];

// ---- packed f32x2 helpers (sm_103a FFMA2) ----
__device__ __forceinline__ unsigned long long pack2(float lo, float hi) {
    unsigned long long r;
    asm("mov.b64 %0, {%1, %2};" : "=l"(r) : "f"(lo), "f"(hi));
    return r;
}
#define FMA2(d, a, b, c) \
    asm("fma.rn.f32x2 %0, %1, %2, %3;" : "=l"(d) : "l"(a), "l"(b), "l"(c))
#define UNPACK2(lo, hi, v) \
    asm("mov.b64 {%0, %1}, %2;" : "=f"(lo), "=f"(hi) : "l"(v))

// ---- init: zero counts + detect edge_index dtype (merged launch) ----
// int64 values < 2^32 (node ids 0..NN-1): every odd 32-bit word is zero.
__global__ void k_init(const int* __restrict__ raw) {
    int i = blockIdx.x * blockDim.x + threadIdx.x;
    if (i < NN) g_cnt[i] = 0;
    if (i == 0) {
        int is64 = 1;
        for (int w = 1; w < 64; w += 2)
            if (raw[w] != 0) { is64 = 0; break; }
        g_is64 = is64;
    }
}

__device__ __forceinline__ int load_dst(const int* __restrict__ raw, int e) {
    if (g_is64) return (int)((const long long*)raw)[NE + e];
    return raw[NE + e];
}

__device__ __forceinline__ void load_edge(const int* __restrict__ raw, int e,
                                          int& src, int& dst) {
    if (g_is64) {
        const long long* e64 = (const long long*)raw;
        src = (int)e64[e];
        dst = (int)e64[NE + e];
    } else {
        src = raw[e];
        dst = raw[NE + e];
    }
}

// ---- CSR build ----
__global__ void k_count(const int* __restrict__ raw) {
    int e = blockIdx.x * blockDim.x + threadIdx.x;
    if (e < NE) {
        int dst = load_dst(raw, e);
        if ((unsigned)dst < NN) atomicAdd(&g_cnt[dst], 1);
    }
}

__global__ void k_scanA() {
    __shared__ int s[256];
    int tid = threadIdx.x;
    int i = blockIdx.x * 256 + tid;
    int v = (i < NN) ? g_cnt[i] : 0;
    s[tid] = v;
    __syncthreads();
    for (int off = 1; off < 256; off <<= 1) {
        int t = (tid >= off) ? s[tid - off] : 0;
        __syncthreads();
        s[tid] += t;
        __syncthreads();
    }
    if (i < NN) g_tmp[i] = s[tid];
    if (tid == 255) g_bsums[blockIdx.x] = s[255];
}

__global__ void k_scanB() {
    __shared__ int s[512];
    int tid = threadIdx.x;
    int v = (tid < NBS) ? g_bsums[tid] : 0;
    s[tid] = v;
    __syncthreads();
    for (int off = 1; off < 512; off <<= 1) {
        int t = (tid >= off) ? s[tid - off] : 0;
        __syncthreads();
        s[tid] += t;
        __syncthreads();
    }
    if (tid < NBS) g_boff[tid] = s[tid] - v;      // exclusive
    if (tid == NBS - 1) g_boff[NBS] = s[tid];     // total
}

__global__ void k_scanC() {
    int i = blockIdx.x * 256 + threadIdx.x;
    if (i < NN) {
        int ex = g_tmp[i] - g_cnt[i] + g_boff[blockIdx.x];
        g_row[i] = ex;
        g_cur[i] = ex;
    }
    if (i == 0) g_row[NN] = g_boff[NBS];
}

__global__ void k_fill(const int* __restrict__ raw) {
    int e = blockIdx.x * blockDim.x + threadIdx.x;
    if (e < NE) {
        int src, dst;
        load_edge(raw, e, src, dst);
        if ((unsigned)dst < NN && (unsigned)src < NN) {
            int idx = atomicAdd(&g_cur[dst], 1);
            if ((unsigned)idx < NE) g_col[idx] = src;
        }
    }
}

// ---- aggregation: 16 lanes per node, gather neighbor rows, unroll x4 ----
template <int LAYER>
__global__ void k_gather(const float* __restrict__ xparam) {
    int gid = blockIdx.x * blockDim.x + threadIdx.x;
    int node = gid >> 4;
    int lane = gid & 15;
    if (node >= NN) return;
    const float* src_base = (LAYER == 1) ? xparam : (const float*)g_h;
    int s = g_row[node];
    int e = g_row[node + 1];
    float4 acc = make_float4(0.f, 0.f, 0.f, 0.f);
    const float4* xv = (const float4*)src_base;
    int j = s;
    for (; j + 3 < e; j += 4) {
        int c0 = g_col[j], c1 = g_col[j + 1], c2 = g_col[j + 2], c3 = g_col[j + 3];
        float4 v0 = __ldg(&xv[c0 * 16 + lane]);
        float4 v1 = __ldg(&xv[c1 * 16 + lane]);
        float4 v2 = __ldg(&xv[c2 * 16 + lane]);
        float4 v3 = __ldg(&xv[c3 * 16 + lane]);
        acc.x += (v0.x + v1.x) + (v2.x + v3.x);
        acc.y += (v0.y + v1.y) + (v2.y + v3.y);
        acc.z += (v0.z + v1.z) + (v2.z + v3.z);
        acc.w += (v0.w + v1.w) + (v2.w + v3.w);
    }
    for (; j < e; j++) {
        int c = g_col[j];
        float4 v = __ldg(&xv[c * 16 + lane]);
        acc.x += v.x; acc.y += v.y; acc.z += v.z; acc.w += v.w;
    }
    ((float4*)g_agg)[node * 16 + lane] = acc;
}

// ---- fused SAGE layer with packed f32x2 FMA ----
// LAYER 1: src = xparam, dst = g_h.  LAYER 2: src = g_h, dst = g_h2.
template <int LAYER>
__global__ void __launch_bounds__(256) k_dense(
        const float* __restrict__ xparam,
        const float* __restrict__ Wl, const float* __restrict__ Wr,
        const float* __restrict__ b) {
    __shared__ __align__(16) float sWl[64 * 64];   // transposed: [k][j]
    __shared__ __align__(16) float sWr[64 * 64];
    __shared__ __align__(16) float sb[64];
    int tid = threadIdx.x;
    for (int idx = tid; idx < 4096; idx += 256) {
        int k = idx >> 6, j = idx & 63;
        sWl[idx] = Wl[j * 64 + k];
        sWr[idx] = Wr[j * 64 + k];
    }
    if (tid < 64) sb[tid] = b[tid];
    __syncthreads();

    int node = blockIdx.x * 256 + tid;
    if (node >= NN) return;

    const float* src = (LAYER == 1) ? xparam : (const float*)g_h;
    float* dst = (LAYER == 1) ? (float*)g_h : (float*)g_h2;

    int deg = g_row[node + 1] - g_row[node];
    float inv = 1.0f / (float)(deg > 1 ? deg : 1);

    // 64 accumulators as 32 packed f32x2
    unsigned long long acc[32];
#pragma unroll
    for (int j2 = 0; j2 < 32; j2++) acc[j2] = pack2(sb[2 * j2], sb[2 * j2 + 1]);

    const float4* xr = (const float4*)(src + (size_t)node * 64);
    const float4* ar = (const float4*)((const float*)g_agg + (size_t)node * 64);

#pragma unroll 1
    for (int k4 = 0; k4 < 16; k4++) {
        float4 xv = xr[k4];
        float4 av = ar[k4];
        float xs[4] = {xv.x, xv.y, xv.z, xv.w};
        float ms[4] = {av.x * inv, av.y * inv, av.z * inv, av.w * inv};
#pragma unroll
        for (int kk = 0; kk < 4; kk++) {
            int k = k4 * 4 + kk;
            unsigned long long xx = pack2(xs[kk], xs[kk]);
            unsigned long long mm = pack2(ms[kk], ms[kk]);
            const ulonglong2* wlr = (const ulonglong2*)(sWl + k * 64);
            const ulonglong2* wrr = (const ulonglong2*)(sWr + k * 64);
#pragma unroll
            for (int j8 = 0; j8 < 16; j8++) {   // 16 x 16B = 64 floats
                ulonglong2 wl = wlr[j8];
                ulonglong2 wr = wrr[j8];
                FMA2(acc[2 * j8],     mm, wl.x, acc[2 * j8]);
                FMA2(acc[2 * j8],     xx, wr.x, acc[2 * j8]);
                FMA2(acc[2 * j8 + 1], mm, wl.y, acc[2 * j8 + 1]);
                FMA2(acc[2 * j8 + 1], xx, wr.y, acc[2 * j8 + 1]);
            }
        }
    }

    float4* o = (float4*)(dst + (size_t)node * 64);
#pragma unroll
    for (int j4 = 0; j4 < 16; j4++) {
        float a0, a1, a2, a3;
        UNPACK2(a0, a1, acc[2 * j4]);
        UNPACK2(a2, a3, acc[2 * j4 + 1]);
        float4 v;
        v.x = fmaxf(a0, 0.f);
        v.y = fmaxf(a1, 0.f);
        v.z = fmaxf(a2, 0.f);
        v.w = fmaxf(a3, 0.f);
        o[j4] = v;
    }
}

// ---- output head: out = g_h2 @ W_out.T + b_out  (10 classes) ----
__global__ void __launch_bounds__(256) k_out(
        const float* __restrict__ Wo, const float* __restrict__ bo,
        float* __restrict__ out) {
    __shared__ float sW[640];
    __shared__ float sbo[10];
    int tid = threadIdx.x;
    for (int i = tid; i < 640; i += 256) sW[i] = Wo[i];
    if (tid < 10) sbo[tid] = bo[tid];
    __syncthreads();

    int node = blockIdx.x * 256 + tid;
    if (node >= NN) return;

    float4 xr[16];
    const float4* hp = (const float4*)((const float*)g_h2 + (size_t)node * 64);
#pragma unroll
    for (int i = 0; i < 16; i++) xr[i] = hp[i];

    const float4* w4 = (const float4*)sW;
#pragma unroll
    for (int c = 0; c < 10; c++) {
        float acc = sbo[c];
#pragma unroll
        for (int k4 = 0; k4 < 16; k4++) {
            float4 w = w4[c * 16 + k4];
            acc += xr[k4].x * w.x + xr[k4].y * w.y + xr[k4].z * w.z + xr[k4].w * w.w;
        }
        out[(size_t)node * 10 + c] = acc;
    }
}

extern "C" void kernel_launch(void* const* d_in, const int* in_sizes, int n_in,
                              void* d_out, int out_size) {
    const float* x       = (const float*)d_in[0];
    const int* ei_raw    = (const int*)d_in[1];   // int32 OR int64 (detected on device)
    const float* W1l     = (const float*)d_in[2];
    const float* W1r     = (const float*)d_in[3];
    const float* b1      = (const float*)d_in[4];
    const float* W2l     = (const float*)d_in[5];
    const float* W2r     = (const float*)d_in[6];
    const float* b2      = (const float*)d_in[7];
    const float* Wo      = (const float*)d_in[8];
    const float* bo      = (const float*)d_in[9];
    float* out           = (float*)d_out;

    // CSR build (zero+detect merged; reused by both layers)
    k_init<<<(NN + 255) / 256, 256>>>(ei_raw);
    k_count<<<(NE + 255) / 256, 256>>>(ei_raw);
    k_scanA<<<NBS, 256>>>();
    k_scanB<<<1, 512>>>();
    k_scanC<<<NBS, 256>>>();
    k_fill<<<(NE + 255) / 256, 256>>>(ei_raw);

    // Layer 1
    k_gather<1><<<(NN * 16 + 255) / 256, 256>>>(x);
    k_dense<1><<<(NN + 255) / 256, 256>>>(x, W1l, W1r, b1);
    // Layer 2
    k_gather<2><<<(NN * 16 + 255) / 256, 256>>>(x);
    k_dense<2><<<(NN + 255) / 256, 256>>>(x, W2l, W2r, b2);
    // Head
    k_out<<<(NN + 255) / 256, 256>>>(Wo, bo, out);
}